// round 6
// baseline (speedup 1.0000x reference)
#include <cuda_runtime.h>
#include <cstdint>

// TransD round 6: hybrid x2 — 4 elems/warp (2 via LDG.128, 2 via cp.async.bulk).
// out[b] = rp * (dot(hp,h) - dot(tp,t)) + (h - t) + r
// ENT_DIM = REL_DIM = 128, BATCH = 16384.

#define BATCH 16384
#define WARPS_PER_BLOCK 8
#define ELEMS_PER_WARP 4
#define ROW_BYTES 512

__device__ __forceinline__ float warp_sum(float v) {
    v += __shfl_xor_sync(0xFFFFFFFFu, v, 16);
    v += __shfl_xor_sync(0xFFFFFFFFu, v, 8);
    v += __shfl_xor_sync(0xFFFFFFFFu, v, 4);
    v += __shfl_xor_sync(0xFFFFFFFFu, v, 2);
    v += __shfl_xor_sync(0xFFFFFFFFu, v, 1);
    return v;
}

__device__ __forceinline__ uint32_t smem_u32(const void* p) {
    uint32_t a;
    asm("{ .reg .u64 t; cvta.to.shared.u64 t, %1; cvt.u32.u64 %0, t; }"
        : "=r"(a) : "l"(p));
    return a;
}

__device__ __forceinline__ void bulk_ld(uint32_t s_dst, const void* g_src,
                                        uint32_t bytes, uint32_t mbar) {
    asm volatile(
        "cp.async.bulk.shared::cta.global.mbarrier::complete_tx::bytes "
        "[%0], [%1], %2, [%3];\n"
        :: "r"(s_dst), "l"(g_src), "r"(bytes), "r"(mbar) : "memory");
}

__device__ __forceinline__ void mbar_init(uint32_t mbar, uint32_t count) {
    asm volatile("mbarrier.init.shared.b64 [%0], %1;\n" :: "r"(mbar), "r"(count) : "memory");
}

__device__ __forceinline__ void mbar_expect_tx(uint32_t mbar, uint32_t bytes) {
    asm volatile("mbarrier.arrive.expect_tx.shared.b64 _, [%0], %1;\n"
                 :: "r"(mbar), "r"(bytes) : "memory");
}

__device__ __forceinline__ void mbar_wait(uint32_t mbar, uint32_t parity) {
    uint32_t done;
    asm volatile(
        "{\n\t"
        ".reg .pred p;\n\t"
        "mbarrier.try_wait.parity.acquire.cta.shared::cta.b64 p, [%1], %2;\n\t"
        "selp.b32 %0, 1, 0, p;\n\t"
        "}"
        : "=r"(done) : "r"(mbar), "r"(parity) : "memory");
    if (!done) {
        asm volatile(
            "{\n\t"
            ".reg .pred P1;\n\t"
            "WAIT_LOOP_%=:\n\t"
            "mbarrier.try_wait.parity.acquire.cta.shared::cta.b64 P1, [%0], %1, 0x989680;\n\t"
            "@P1 bra.uni WAIT_DONE_%=;\n\t"
            "bra.uni WAIT_LOOP_%=;\n\t"
            "WAIT_DONE_%=:\n\t"
            "}"
            :: "r"(mbar), "r"(parity) : "memory");
    }
}

__global__ __launch_bounds__(256)
void transd_kernel(const int* __restrict__ head,
                   const int* __restrict__ relation,
                   const int* __restrict__ tail,
                   const char* __restrict__ ent_emb,
                   const char* __restrict__ ent_map_emb,
                   const float4* __restrict__ rel_emb,
                   const float4* __restrict__ rel_map_emb,
                   float4* __restrict__ out)
{
    // Bulk path: 2 elems x 4 rows x 512B = 4KB per warp -> 32KB per block.
    __shared__ __align__(128) float4 buf[WARPS_PER_BLOCK][8][32];
    __shared__ __align__(8) unsigned long long mbar_store[WARPS_PER_BLOCK];

    const int wid  = threadIdx.x >> 5;
    const int lane = threadIdx.x & 31;
    const int warp_global = blockIdx.x * WARPS_PER_BLOCK + wid;

    const int b0 = warp_global * ELEMS_PER_WARP;  // LDG elem
    const int b1 = b0 + 1;                        // LDG elem
    const int b2 = b0 + 2;                        // bulk elem
    const int b3 = b0 + 3;                        // bulk elem

    const int h0 = __ldg(&head[b0]), h1 = __ldg(&head[b1]);
    const int h2 = __ldg(&head[b2]), h3 = __ldg(&head[b3]);
    const int t0 = __ldg(&tail[b0]), t1 = __ldg(&tail[b1]);
    const int t2 = __ldg(&tail[b2]), t3 = __ldg(&tail[b3]);
    const int r0 = __ldg(&relation[b0]), r1 = __ldg(&relation[b1]);

    const uint32_t mbar   = smem_u32(&mbar_store[wid]);
    const uint32_t s_row0 = smem_u32(&buf[wid][0][0]);

    // --- Path A: elems 2,3 via TMA bulk engine (async into smem) ---
    if (lane == 0) {
        mbar_init(mbar, 1);
        asm volatile("fence.proxy.async.shared::cta;\n" ::: "memory");
        mbar_expect_tx(mbar, 8 * ROW_BYTES);
        bulk_ld(s_row0 + 0 * ROW_BYTES, ent_emb     + (long)h2 * ROW_BYTES, ROW_BYTES, mbar);
        bulk_ld(s_row0 + 1 * ROW_BYTES, ent_emb     + (long)t2 * ROW_BYTES, ROW_BYTES, mbar);
        bulk_ld(s_row0 + 2 * ROW_BYTES, ent_map_emb + (long)h2 * ROW_BYTES, ROW_BYTES, mbar);
        bulk_ld(s_row0 + 3 * ROW_BYTES, ent_map_emb + (long)t2 * ROW_BYTES, ROW_BYTES, mbar);
        bulk_ld(s_row0 + 4 * ROW_BYTES, ent_emb     + (long)h3 * ROW_BYTES, ROW_BYTES, mbar);
        bulk_ld(s_row0 + 5 * ROW_BYTES, ent_emb     + (long)t3 * ROW_BYTES, ROW_BYTES, mbar);
        bulk_ld(s_row0 + 6 * ROW_BYTES, ent_map_emb + (long)h3 * ROW_BYTES, ROW_BYTES, mbar);
        bulk_ld(s_row0 + 7 * ROW_BYTES, ent_map_emb + (long)t3 * ROW_BYTES, ROW_BYTES, mbar);
    }

    // --- Path B: elems 0,1 via LDG.128 (registers) ---
    const float4* e4  = (const float4*)ent_emb;
    const float4* em4 = (const float4*)ent_map_emb;
    const long ho0 = (long)h0 * 32 + lane;
    const long to0 = (long)t0 * 32 + lane;
    const long ho1 = (long)h1 * 32 + lane;
    const long to1 = (long)t1 * 32 + lane;
    const float4 vh0  = __ldg(&e4[ho0]);
    const float4 vt0  = __ldg(&e4[to0]);
    const float4 vh1  = __ldg(&e4[ho1]);
    const float4 vt1  = __ldg(&e4[to1]);
    const float4 vhp0 = __ldg(&em4[ho0]);
    const float4 vtp0 = __ldg(&em4[to0]);
    const float4 vhp1 = __ldg(&em4[ho1]);
    const float4 vtp1 = __ldg(&em4[to1]);

    // Relations for LDG elems (L2-resident).
    const long ro0 = (long)r0 * 32 + lane;
    const long ro1 = (long)r1 * 32 + lane;
    const float4 vr0  = __ldg(&rel_emb[ro0]);
    const float4 vr1  = __ldg(&rel_emb[ro1]);
    const float4 vrp0 = __ldg(&rel_map_emb[ro0]);
    const float4 vrp1 = __ldg(&rel_map_emb[ro1]);

    // --- Compute elems 0,1 while bulk copies fly ---
    float dh0 = vh0.x * vhp0.x + vh0.y * vhp0.y + vh0.z * vhp0.z + vh0.w * vhp0.w;
    float dt0 = vt0.x * vtp0.x + vt0.y * vtp0.y + vt0.z * vtp0.z + vt0.w * vtp0.w;
    float dh1 = vh1.x * vhp1.x + vh1.y * vhp1.y + vh1.z * vhp1.z + vh1.w * vhp1.w;
    float dt1 = vt1.x * vtp1.x + vt1.y * vtp1.y + vt1.z * vtp1.z + vt1.w * vtp1.w;
    const float d0 = warp_sum(dh0 - dt0);
    const float d1 = warp_sum(dh1 - dt1);

    float4 o0, o1;
    o0.x = fmaf(vrp0.x, d0, vh0.x - vt0.x + vr0.x);
    o0.y = fmaf(vrp0.y, d0, vh0.y - vt0.y + vr0.y);
    o0.z = fmaf(vrp0.z, d0, vh0.z - vt0.z + vr0.z);
    o0.w = fmaf(vrp0.w, d0, vh0.w - vt0.w + vr0.w);
    o1.x = fmaf(vrp1.x, d1, vh1.x - vt1.x + vr1.x);
    o1.y = fmaf(vrp1.y, d1, vh1.y - vt1.y + vr1.y);
    o1.z = fmaf(vrp1.z, d1, vh1.z - vt1.z + vr1.z);
    o1.w = fmaf(vrp1.w, d1, vh1.w - vt1.w + vr1.w);
    out[(long)b0 * 32 + lane] = o0;
    out[(long)b1 * 32 + lane] = o1;

    // --- Wait for bulk elems 2,3; fetch their relations (L2-fast) now ---
    const int r2 = __ldg(&relation[b2]), r3 = __ldg(&relation[b3]);
    const long ro2 = (long)r2 * 32 + lane;
    const long ro3 = (long)r3 * 32 + lane;
    const float4 vr2  = __ldg(&rel_emb[ro2]);
    const float4 vr3  = __ldg(&rel_emb[ro3]);
    const float4 vrp2 = __ldg(&rel_map_emb[ro2]);
    const float4 vrp3 = __ldg(&rel_map_emb[ro3]);

    __syncwarp();
    mbar_wait(mbar, 0);

    const float4 vh2  = buf[wid][0][lane];
    const float4 vt2  = buf[wid][1][lane];
    const float4 vhp2 = buf[wid][2][lane];
    const float4 vtp2 = buf[wid][3][lane];
    const float4 vh3  = buf[wid][4][lane];
    const float4 vt3  = buf[wid][5][lane];
    const float4 vhp3 = buf[wid][6][lane];
    const float4 vtp3 = buf[wid][7][lane];

    float dh2 = vh2.x * vhp2.x + vh2.y * vhp2.y + vh2.z * vhp2.z + vh2.w * vhp2.w;
    float dt2 = vt2.x * vtp2.x + vt2.y * vtp2.y + vt2.z * vtp2.z + vt2.w * vtp2.w;
    float dh3 = vh3.x * vhp3.x + vh3.y * vhp3.y + vh3.z * vhp3.z + vh3.w * vhp3.w;
    float dt3 = vt3.x * vtp3.x + vt3.y * vtp3.y + vt3.z * vtp3.z + vt3.w * vtp3.w;
    const float d2 = warp_sum(dh2 - dt2);
    const float d3 = warp_sum(dh3 - dt3);

    float4 o2, o3;
    o2.x = fmaf(vrp2.x, d2, vh2.x - vt2.x + vr2.x);
    o2.y = fmaf(vrp2.y, d2, vh2.y - vt2.y + vr2.y);
    o2.z = fmaf(vrp2.z, d2, vh2.z - vt2.z + vr2.z);
    o2.w = fmaf(vrp2.w, d2, vh2.w - vt2.w + vr2.w);
    o3.x = fmaf(vrp3.x, d3, vh3.x - vt3.x + vr3.x);
    o3.y = fmaf(vrp3.y, d3, vh3.y - vt3.y + vr3.y);
    o3.z = fmaf(vrp3.z, d3, vh3.z - vt3.z + vr3.z);
    o3.w = fmaf(vrp3.w, d3, vh3.w - vt3.w + vr3.w);
    out[(long)b2 * 32 + lane] = o2;
    out[(long)b3 * 32 + lane] = o3;
}

extern "C" void kernel_launch(void* const* d_in, const int* in_sizes, int n_in,
                              void* d_out, int out_size)
{
    const int*    head    = (const int*)d_in[0];
    const int*    rel     = (const int*)d_in[1];
    const int*    tail    = (const int*)d_in[2];
    const char*   ent     = (const char*)d_in[3];
    const char*   ent_map = (const char*)d_in[4];
    const float4* rel_emb = (const float4*)d_in[5];
    const float4* rel_map = (const float4*)d_in[6];
    float4*       out     = (float4*)d_out;

    const int threads = 256;  // 8 warps x 4 elems = 32 elems/block
    const int blocks  = BATCH / (WARPS_PER_BLOCK * ELEMS_PER_WARP);  // 512
    transd_kernel<<<blocks, threads>>>(head, rel, tail, ent, ent_map,
                                       rel_emb, rel_map, out);
}

// round 7
// speedup vs baseline: 1.2050x; 1.2050x over previous
#include <cuda_runtime.h>
#include <cstdint>

// TransD round 7: dual-engine by warp parity.
// out[b] = rp * (dot(hp,h) - dot(tp,t)) + (h - t) + r
// ENT_DIM = REL_DIM = 128, BATCH = 16384.
//
// 16384 warps, ONE batch element each (min lifetime, max warp concurrency).
// Even warps gather their 4 entity rows via LDG.128 (L1-miss path, registers);
// odd warps gather via cp.async.bulk into smem (TMA/bulk-engine path).
// Both per-SM memory resources stay loaded simultaneously (R5's insight),
// without R5's per-warp two-phase serialization.

#define BATCH 16384
#define WARPS_PER_BLOCK 8
#define ROW_BYTES 512

__device__ __forceinline__ float warp_sum(float v) {
    v += __shfl_xor_sync(0xFFFFFFFFu, v, 16);
    v += __shfl_xor_sync(0xFFFFFFFFu, v, 8);
    v += __shfl_xor_sync(0xFFFFFFFFu, v, 4);
    v += __shfl_xor_sync(0xFFFFFFFFu, v, 2);
    v += __shfl_xor_sync(0xFFFFFFFFu, v, 1);
    return v;
}

__device__ __forceinline__ uint32_t smem_u32(const void* p) {
    uint32_t a;
    asm("{ .reg .u64 t; cvta.to.shared.u64 t, %1; cvt.u32.u64 %0, t; }"
        : "=r"(a) : "l"(p));
    return a;
}

__device__ __forceinline__ void bulk_ld(uint32_t s_dst, const void* g_src,
                                        uint32_t bytes, uint32_t mbar) {
    asm volatile(
        "cp.async.bulk.shared::cta.global.mbarrier::complete_tx::bytes "
        "[%0], [%1], %2, [%3];\n"
        :: "r"(s_dst), "l"(g_src), "r"(bytes), "r"(mbar) : "memory");
}

__device__ __forceinline__ void mbar_init(uint32_t mbar, uint32_t count) {
    asm volatile("mbarrier.init.shared.b64 [%0], %1;\n" :: "r"(mbar), "r"(count) : "memory");
}

__device__ __forceinline__ void mbar_expect_tx(uint32_t mbar, uint32_t bytes) {
    asm volatile("mbarrier.arrive.expect_tx.shared.b64 _, [%0], %1;\n"
                 :: "r"(mbar), "r"(bytes) : "memory");
}

__device__ __forceinline__ void mbar_wait(uint32_t mbar, uint32_t parity) {
    uint32_t done;
    asm volatile(
        "{\n\t"
        ".reg .pred p;\n\t"
        "mbarrier.try_wait.parity.acquire.cta.shared::cta.b64 p, [%1], %2;\n\t"
        "selp.b32 %0, 1, 0, p;\n\t"
        "}"
        : "=r"(done) : "r"(mbar), "r"(parity) : "memory");
    if (!done) {
        asm volatile(
            "{\n\t"
            ".reg .pred P1;\n\t"
            "WAIT_LOOP_%=:\n\t"
            "mbarrier.try_wait.parity.acquire.cta.shared::cta.b64 P1, [%0], %1, 0x989680;\n\t"
            "@P1 bra.uni WAIT_DONE_%=;\n\t"
            "bra.uni WAIT_LOOP_%=;\n\t"
            "WAIT_DONE_%=:\n\t"
            "}"
            :: "r"(mbar), "r"(parity) : "memory");
    }
}

__global__ __launch_bounds__(256)
void transd_kernel(const int* __restrict__ head,
                   const int* __restrict__ relation,
                   const int* __restrict__ tail,
                   const char* __restrict__ ent_emb,
                   const char* __restrict__ ent_map_emb,
                   const float4* __restrict__ rel_emb,
                   const float4* __restrict__ rel_map_emb,
                   float4* __restrict__ out)
{
    // Only odd warps (4 per block) use a smem slab: 4 rows x 512B = 2KB each.
    __shared__ __align__(128) float4 buf[WARPS_PER_BLOCK / 2][4][32];
    __shared__ __align__(8) unsigned long long mbar_store[WARPS_PER_BLOCK / 2];

    const int wid  = threadIdx.x >> 5;
    const int lane = threadIdx.x & 31;
    const int warp_global = blockIdx.x * WARPS_PER_BLOCK + wid;
    const int b = warp_global;  // one element per warp

    const int hidx = __ldg(&head[b]);
    const int tidx = __ldg(&tail[b]);
    const int ridx = __ldg(&relation[b]);

    // Relation rows (L2-resident) — issue early on both paths.
    const long ro = (long)ridx * 32 + lane;
    const float4 vr  = __ldg(&rel_emb[ro]);
    const float4 vrp = __ldg(&rel_map_emb[ro]);

    float4 vh, vt, vhp, vtp;

    if (wid & 1) {
        // ---- Bulk-engine path ----
        const int slab = wid >> 1;
        const uint32_t mbar   = smem_u32(&mbar_store[slab]);
        const uint32_t s_row0 = smem_u32(&buf[slab][0][0]);
        if (lane == 0) {
            mbar_init(mbar, 1);
            asm volatile("fence.proxy.async.shared::cta;\n" ::: "memory");
            mbar_expect_tx(mbar, 4 * ROW_BYTES);
            bulk_ld(s_row0 + 0 * ROW_BYTES, ent_emb     + (long)hidx * ROW_BYTES, ROW_BYTES, mbar);
            bulk_ld(s_row0 + 1 * ROW_BYTES, ent_emb     + (long)tidx * ROW_BYTES, ROW_BYTES, mbar);
            bulk_ld(s_row0 + 2 * ROW_BYTES, ent_map_emb + (long)hidx * ROW_BYTES, ROW_BYTES, mbar);
            bulk_ld(s_row0 + 3 * ROW_BYTES, ent_map_emb + (long)tidx * ROW_BYTES, ROW_BYTES, mbar);
        }
        __syncwarp();
        mbar_wait(mbar, 0);
        vh  = buf[slab][0][lane];
        vt  = buf[slab][1][lane];
        vhp = buf[slab][2][lane];
        vtp = buf[slab][3][lane];
    } else {
        // ---- LDG.128 path ----
        const float4* e4  = (const float4*)ent_emb;
        const float4* em4 = (const float4*)ent_map_emb;
        const long ho = (long)hidx * 32 + lane;
        const long to = (long)tidx * 32 + lane;
        vh  = __ldg(&e4[ho]);
        vt  = __ldg(&e4[to]);
        vhp = __ldg(&em4[ho]);
        vtp = __ldg(&em4[to]);
    }

    float dh = vh.x * vhp.x + vh.y * vhp.y + vh.z * vhp.z + vh.w * vhp.w;
    float dt = vt.x * vtp.x + vt.y * vtp.y + vt.z * vtp.z + vt.w * vtp.w;
    const float d = warp_sum(dh - dt);

    float4 o;
    o.x = fmaf(vrp.x, d, vh.x - vt.x + vr.x);
    o.y = fmaf(vrp.y, d, vh.y - vt.y + vr.y);
    o.z = fmaf(vrp.z, d, vh.z - vt.z + vr.z);
    o.w = fmaf(vrp.w, d, vh.w - vt.w + vr.w);

    out[(long)b * 32 + lane] = o;
}

extern "C" void kernel_launch(void* const* d_in, const int* in_sizes, int n_in,
                              void* d_out, int out_size)
{
    const int*    head    = (const int*)d_in[0];
    const int*    rel     = (const int*)d_in[1];
    const int*    tail    = (const int*)d_in[2];
    const char*   ent     = (const char*)d_in[3];
    const char*   ent_map = (const char*)d_in[4];
    const float4* rel_emb = (const float4*)d_in[5];
    const float4* rel_map = (const float4*)d_in[6];
    float4*       out     = (float4*)d_out;

    const int threads = 256;                    // 8 warps = 8 elems/block
    const int blocks  = BATCH / WARPS_PER_BLOCK;  // 2048
    transd_kernel<<<blocks, threads>>>(head, rel, tail, ent, ent_map,
                                       rel_emb, rel_map, out);
}